// round 13
// baseline (speedup 1.0000x reference)
#include <cuda_runtime.h>
#include <cuda_bf16.h>
#include <cstdint>

#define EMBED 1024
#define HID   128
#define NQ    65536
#define NP    512
#define MT    128          // M rows per CTA
#define KC    32           // K elems per pipeline stage
#define NITER (EMBED / KC) // 32
#define STAGES 4
#define NTHR  512
#define APAD 36            // fp32 per A smem row (144B stride, 16B-aligned)
#define BPAD 40            // bf16 per B smem row (80B stride, 16B-aligned)
#define A_STAGE_FLOATS (MT * APAD)        // 4608 floats = 18432 B
#define B_STAGE_HALFS  (HID * BPAD)       // 5120 bf16  = 10240 B
#define DYN_SMEM (STAGES * (A_STAGE_FLOATS * 4 + B_STAGE_HALFS * 2))  // 114688 B

// Scratch: W1 top half transposed to bf16 [n][k]; Pb = proto @ W1_bot + b1.
__device__ __align__(16) __nv_bfloat16 g_W1t[HID * EMBED];
__device__ __align__(16) float g_Pb[NP * HID];

// ---------------------------------------------------------------------------
__device__ __forceinline__ uint32_t smem_u32(const void* p) {
    uint32_t a;
    asm("{ .reg .u64 t; cvta.to.shared.u64 t, %1; cvt.u32.u64 %0, t; }" : "=r"(a) : "l"(p));
    return a;
}
__device__ __forceinline__ void cp_async16(uint32_t dst, const void* src) {
    asm volatile("cp.async.cg.shared.global [%0], [%1], 16;" :: "r"(dst), "l"(src) : "memory");
}
#define CP_COMMIT() asm volatile("cp.async.commit_group;" ::: "memory")
#define CP_WAIT2()  asm volatile("cp.async.wait_group 2;" ::: "memory")

__device__ __forceinline__ uint32_t cvt_bf2(float hi, float lo) {
    uint32_t r;
    asm("cvt.rn.bf16x2.f32 %0, %1, %2;" : "=r"(r) : "f"(hi), "f"(lo));
    return r;
}

// ---------------------------------------------------------------------------
// Kernel 1: coalesced tile transpose W1_top (fp32 [k][n]) -> g_W1t (bf16 [n][k])
// ---------------------------------------------------------------------------
__global__ void w1t_kernel(const float* __restrict__ W1) {
    __shared__ float tile[32][33];
    int kb = blockIdx.x * 32, nb = blockIdx.y * 32;
    int tx = threadIdx.x, ty = threadIdx.y;
#pragma unroll
    for (int r = ty; r < 32; r += 8)
        tile[r][tx] = W1[(size_t)(kb + r) * HID + nb + tx];
    __syncthreads();
#pragma unroll
    for (int r = ty; r < 32; r += 8)
        g_W1t[(size_t)(nb + r) * EMBED + kb + tx] = __float2bfloat16(tile[tx][r]);
}

// ---------------------------------------------------------------------------
// Kernel 2: Pb[p][j] = proto[p] @ W1_bottom[:, j] + b1[j]
// ---------------------------------------------------------------------------
__global__ void proto_kernel(const float* __restrict__ proto,
                             const float* __restrict__ W1,
                             const float* __restrict__ b1) {
    __shared__ float sp[4 * EMBED];
    __shared__ float spart[4][HID];
    int t  = threadIdx.x;
    int j  = t & (HID - 1);
    int kh = t >> 7;
    int p0 = blockIdx.x * 4;

    for (int i = t * 4; i < 4 * EMBED; i += 256 * 4)
        *(float4*)(sp + i) = *(const float4*)(proto + (size_t)p0 * EMBED + i);
    __syncthreads();

    float a0 = 0.f, a1 = 0.f, a2 = 0.f, a3 = 0.f;
    int kbeg = kh * (EMBED / 2);
#pragma unroll 4
    for (int k = kbeg; k < kbeg + EMBED / 2; k++) {
        float w = W1[(size_t)(EMBED + k) * HID + j];
        a0 += sp[0 * EMBED + k] * w;
        a1 += sp[1 * EMBED + k] * w;
        a2 += sp[2 * EMBED + k] * w;
        a3 += sp[3 * EMBED + k] * w;
    }
    if (kh == 1) { spart[0][j] = a0; spart[1][j] = a1; spart[2][j] = a2; spart[3][j] = a3; }
    __syncthreads();
    if (kh == 0) {
        float bb = b1[j];
        g_Pb[(size_t)(p0 + 0) * HID + j] = a0 + spart[0][j] + bb;
        g_Pb[(size_t)(p0 + 1) * HID + j] = a1 + spart[1][j] + bb;
        g_Pb[(size_t)(p0 + 2) * HID + j] = a2 + spart[2][j] + bb;
        g_Pb[(size_t)(p0 + 3) * HID + j] = a3 + spart[3][j] + bb;
    }
}

// ---------------------------------------------------------------------------
// Kernel 3: fused argmin + pipelined bf16 mma.sync GEMM + epilogue.
// CTA 128x128, 512 threads (16 warps: 4M x 4N, warp tile 32x32).
// cp.async 4-stage pipeline (prefetch depth 3), one __syncthreads per K-iter.
// Argmin runs after pipeline prologue so dist reads overlap the fill.
// ---------------------------------------------------------------------------
__global__ __launch_bounds__(NTHR, 1)
void gemm_kernel(const float* __restrict__ Q,
                 const float* __restrict__ dist,
                 const float* __restrict__ W2,
                 const float* __restrict__ b2,
                 float* __restrict__ out) {
    extern __shared__ __align__(16) char dyn[];
    float*         As = (float*)dyn;                                  // 4 x 128 x APAD
    __nv_bfloat16* Bs = (__nv_bfloat16*)(dyn + STAGES * A_STAGE_FLOATS * 4);

    __shared__ float s_w2[HID];
    __shared__ float s_rowsum[MT];
    __shared__ int   s_idx[MT];

    const int t = threadIdx.x, warp = t >> 5, lane = t & 31;
    const int m0 = blockIdx.x * MT;
    const uint32_t aSm = smem_u32(As);
    const uint32_t bSm = smem_u32(Bs);

    // loader mapping: 4 threads per row (rows 0..127)
    const int lrow = t >> 2, lch = t & 3;
    const float*         qrow = Q + (size_t)(m0 + lrow) * EMBED;
    const __nv_bfloat16* brow = g_W1t + (size_t)lrow * EMBED;

    auto load_stage = [&](int c, int s) {
        const int k0 = c * KC;
        uint32_t aDst = aSm + s * (A_STAGE_FLOATS * 4) + lrow * (APAD * 4);
        uint32_t bDst = bSm + s * (B_STAGE_HALFS * 2) + lrow * (BPAD * 2);
        cp_async16(aDst + lch * 16,       qrow + k0 + lch * 4);        // A cols 0..15
        cp_async16(aDst + (lch + 4) * 16, qrow + k0 + (lch + 4) * 4);  // A cols 16..31
        cp_async16(bDst + lch * 16,       brow + k0 + lch * 8);        // B cols 0..31
    };

    // ---- pipeline prologue: 3 stages in flight before anything else ----
    load_stage(0, 0); CP_COMMIT();
    load_stage(1, 1); CP_COMMIT();
    load_stage(2, 2); CP_COMMIT();

    if (t < HID) s_w2[t] = W2[t];
    if (t < MT)  s_rowsum[t] = 0.f;

    // ---- fused argmin: warp w handles rows w*8 .. w*8+7 (overlaps fill) ----
    for (int i = 0; i < 8; i++) {
        int qi = warp * 8 + i;
        const float* row = dist + (size_t)(m0 + qi) * NP;
        float best = 3.4e38f; int bi = 0;
#pragma unroll
        for (int it = 0; it < 4; it++) {
            int j = it * 128 + lane * 4;
            float4 v = *(const float4*)(row + j);
            if (v.x < best) { best = v.x; bi = j; }
            if (v.y < best) { best = v.y; bi = j + 1; }
            if (v.z < best) { best = v.z; bi = j + 2; }
            if (v.w < best) { best = v.w; bi = j + 3; }
        }
#pragma unroll
        for (int off = 16; off; off >>= 1) {
            float ov = __shfl_down_sync(0xffffffffu, best, off);
            int   oi = __shfl_down_sync(0xffffffffu, bi,   off);
            if (ov < best || (ov == best && oi < bi)) { best = ov; bi = oi; }
        }
        if (lane == 0) s_idx[qi] = bi;
    }

    // ---- accumulators + fragment mapping ----
    float acc[2][4][4];
#pragma unroll
    for (int mi = 0; mi < 2; mi++)
#pragma unroll
        for (int ni = 0; ni < 4; ni++)
#pragma unroll
            for (int r = 0; r < 4; r++) acc[mi][ni][r] = 0.f;

    const int warpM = warp >> 2;   // 0..3 : rows warpM*32
    const int warpN = warp & 3;    // 0..3 : cols warpN*32
    const int g  = lane >> 2;      // 0..7
    const int qd = lane & 3;       // 0..3

    // ---- mainloop ----
    for (int c = 0; c < NITER; c++) {
        const int sc = c & (STAGES - 1);
        CP_WAIT2();                 // stage c landed
        __syncthreads();            // all warps see it; stage c-1 fully consumed

        if (c + 3 < NITER) load_stage(c + 3, (c + 3) & (STAGES - 1));
        CP_COMMIT();

        const float*         A0 = As + sc * A_STAGE_FLOATS;
        const __nv_bfloat16* B0 = Bs + sc * B_STAGE_HALFS;

#pragma unroll
        for (int ks = 0; ks < 2; ks++) {
            const int ko = ks * 16;
            uint32_t a[2][4];
#pragma unroll
            for (int mi = 0; mi < 2; mi++) {
                const float* p1 = A0 + (warpM * 32 + mi * 16 + g) * APAD + ko + qd * 2;
                const float* p2 = p1 + 8 * APAD;
                float2 v;
                v = *(const float2*)(p1);     a[mi][0] = cvt_bf2(v.y, v.x);
                v = *(const float2*)(p2);     a[mi][1] = cvt_bf2(v.y, v.x);
                v = *(const float2*)(p1 + 8); a[mi][2] = cvt_bf2(v.y, v.x);
                v = *(const float2*)(p2 + 8); a[mi][3] = cvt_bf2(v.y, v.x);
            }
            uint32_t b[4][2];
#pragma unroll
            for (int ni = 0; ni < 4; ni++) {
                const __nv_bfloat16* pb = B0 + (warpN * 32 + ni * 8 + g) * BPAD + ko + qd * 2;
                b[ni][0] = *(const uint32_t*)(pb);
                b[ni][1] = *(const uint32_t*)(pb + 8);
            }
#pragma unroll
            for (int mi = 0; mi < 2; mi++)
#pragma unroll
                for (int ni = 0; ni < 4; ni++)
                    asm volatile(
                        "mma.sync.aligned.m16n8k16.row.col.f32.bf16.bf16.f32 "
                        "{%0,%1,%2,%3}, {%4,%5,%6,%7}, {%8,%9}, {%0,%1,%2,%3};\n"
                        : "+f"(acc[mi][ni][0]), "+f"(acc[mi][ni][1]),
                          "+f"(acc[mi][ni][2]), "+f"(acc[mi][ni][3])
                        : "r"(a[mi][0]), "r"(a[mi][1]), "r"(a[mi][2]), "r"(a[mi][3]),
                          "r"(b[ni][0]), "r"(b[ni][1]));
        }
    }

    // ---- epilogue: +Pb[idx], relu, * W2, row-reduce, sigmoid ----
#pragma unroll
    for (int mi = 0; mi < 2; mi++) {
#pragma unroll
        for (int rr = 0; rr < 2; rr++) {
            int rloc = warpM * 32 + mi * 16 + rr * 8 + g;
            const float* Pr = g_Pb + (size_t)s_idx[rloc] * HID;
            float s = 0.f;
#pragma unroll
            for (int ni = 0; ni < 4; ni++) {
                int cc = warpN * 32 + ni * 8 + qd * 2;
                float v0 = acc[mi][ni][rr * 2 + 0] + Pr[cc];
                float v1 = acc[mi][ni][rr * 2 + 1] + Pr[cc + 1];
                s += fmaxf(v0, 0.f) * s_w2[cc] + fmaxf(v1, 0.f) * s_w2[cc + 1];
            }
            atomicAdd(&s_rowsum[rloc], s);
        }
    }
    __syncthreads();
    if (t < MT) {
        float z = s_rowsum[t] + b2[0];
        out[m0 + t] = 1.f / (1.f + __expf(-z));
    }
}

// ---------------------------------------------------------------------------
extern "C" void kernel_launch(void* const* d_in, const int* in_sizes, int n_in,
                              void* d_out, int out_size) {
    const float* Q     = (const float*)d_in[0];   // [65536,1024]
    const float* proto = (const float*)d_in[1];   // [512,1024]
    const float* dist  = (const float*)d_in[2];   // [65536,512]
    const float* W1    = (const float*)d_in[3];   // [2048,128]
    const float* b1    = (const float*)d_in[4];   // [128]
    const float* W2    = (const float*)d_in[5];   // [128,1]
    const float* b2    = (const float*)d_in[6];   // [1]
    float* out = (float*)d_out;                   // [65536]

    static bool attr_set = false;
    if (!attr_set) {
        cudaFuncSetAttribute(gemm_kernel,
                             cudaFuncAttributeMaxDynamicSharedMemorySize, DYN_SMEM);
        attr_set = true;
    }

    w1t_kernel<<<dim3(EMBED / 32, HID / 32), dim3(32, 8)>>>(W1);
    proto_kernel<<<NP / 4, 256>>>(proto, W1, b1);
    gemm_kernel<<<NQ / MT, NTHR, DYN_SMEM>>>(Q, dist, W2, b2, out);
}

// round 14
// speedup vs baseline: 1.0918x; 1.0918x over previous
#include <cuda_runtime.h>
#include <cuda_bf16.h>
#include <cstdint>

#define EMBED 1024
#define HID   128
#define NQ    65536
#define NP    512
#define MT    128          // M rows per CTA
#define KC    32           // K elems per pipeline stage
#define NITER (EMBED / KC) // 32
#define STAGES 3
#define NTHR  256
#define APAD 36            // fp32 per A smem row (144B stride)
#define BPAD 40            // bf16 per B smem row (80B stride)
#define A_STAGE_FLOATS (MT * APAD)        // 4608 fp32  = 18432 B
#define B_STAGE_HALFS  (HID * BPAD)       // 5120 bf16  = 10240 B
#define D_STAGE_FLOATS (4 * NP)           // 2048 fp32  =  8192 B  (4 dist rows/iter)
#define STAGE_BYTES (A_STAGE_FLOATS * 4 + B_STAGE_HALFS * 2 + D_STAGE_FLOATS * 4) // 36864
#define DYN_SMEM (STAGES * STAGE_BYTES)   // 110592 B -> 2 CTAs/SM

// Scratch: W1 top half transposed to bf16 [n][k]; Pb = proto @ W1_bot + b1.
__device__ __align__(16) __nv_bfloat16 g_W1t[HID * EMBED];
__device__ __align__(16) float g_Pb[NP * HID];

// ---------------------------------------------------------------------------
__device__ __forceinline__ uint32_t smem_u32(const void* p) {
    uint32_t a;
    asm("{ .reg .u64 t; cvta.to.shared.u64 t, %1; cvt.u32.u64 %0, t; }" : "=r"(a) : "l"(p));
    return a;
}
__device__ __forceinline__ void cp_async16(uint32_t dst, const void* src) {
    asm volatile("cp.async.cg.shared.global [%0], [%1], 16;" :: "r"(dst), "l"(src) : "memory");
}
#define CP_COMMIT() asm volatile("cp.async.commit_group;" ::: "memory")
#define CP_WAIT1()  asm volatile("cp.async.wait_group 1;" ::: "memory")

__device__ __forceinline__ uint32_t cvt_bf2(float hi, float lo) {
    uint32_t r;
    asm("cvt.rn.bf16x2.f32 %0, %1, %2;" : "=r"(r) : "f"(hi), "f"(lo));
    return r;
}

// ---------------------------------------------------------------------------
// Kernel 1: coalesced tile transpose W1_top (fp32 [k][n]) -> g_W1t (bf16 [n][k])
// ---------------------------------------------------------------------------
__global__ void w1t_kernel(const float* __restrict__ W1) {
    __shared__ float tile[32][33];
    int kb = blockIdx.x * 32, nb = blockIdx.y * 32;
    int tx = threadIdx.x, ty = threadIdx.y;
#pragma unroll
    for (int r = ty; r < 32; r += 8)
        tile[r][tx] = W1[(size_t)(kb + r) * HID + nb + tx];
    __syncthreads();
#pragma unroll
    for (int r = ty; r < 32; r += 8)
        g_W1t[(size_t)(nb + r) * EMBED + kb + tx] = __float2bfloat16(tile[tx][r]);
}

// ---------------------------------------------------------------------------
// Kernel 2: Pb[p][j] = proto[p] @ W1_bottom[:, j] + b1[j]
// ---------------------------------------------------------------------------
__global__ void proto_kernel(const float* __restrict__ proto,
                             const float* __restrict__ W1,
                             const float* __restrict__ b1) {
    __shared__ float sp[4 * EMBED];
    __shared__ float spart[4][HID];
    int t  = threadIdx.x;
    int j  = t & (HID - 1);
    int kh = t >> 7;
    int p0 = blockIdx.x * 4;

    for (int i = t * 4; i < 4 * EMBED; i += 256 * 4)
        *(float4*)(sp + i) = *(const float4*)(proto + (size_t)p0 * EMBED + i);
    __syncthreads();

    float a0 = 0.f, a1 = 0.f, a2 = 0.f, a3 = 0.f;
    int kbeg = kh * (EMBED / 2);
#pragma unroll 4
    for (int k = kbeg; k < kbeg + EMBED / 2; k++) {
        float w = W1[(size_t)(EMBED + k) * HID + j];
        a0 += sp[0 * EMBED + k] * w;
        a1 += sp[1 * EMBED + k] * w;
        a2 += sp[2 * EMBED + k] * w;
        a3 += sp[3 * EMBED + k] * w;
    }
    if (kh == 1) { spart[0][j] = a0; spart[1][j] = a1; spart[2][j] = a2; spart[3][j] = a3; }
    __syncthreads();
    if (kh == 0) {
        float bb = b1[j];
        g_Pb[(size_t)(p0 + 0) * HID + j] = a0 + spart[0][j] + bb;
        g_Pb[(size_t)(p0 + 1) * HID + j] = a1 + spart[1][j] + bb;
        g_Pb[(size_t)(p0 + 2) * HID + j] = a2 + spart[2][j] + bb;
        g_Pb[(size_t)(p0 + 3) * HID + j] = a3 + spart[3][j] + bb;
    }
}

// ---------------------------------------------------------------------------
// Kernel 3: fully-fused pipeline: cp.async stages carry {A tile, B tile,
// 4 dist rows}. Argmin folds from smem inside the mainloop (warps 0-3,
// one row each per iter). bf16 mma.sync GEMM, fused MLP epilogue.
// 256 threads (8 warps: 4M x 2N, warp tile 32x64), 3 stages, 2 CTAs/SM.
// ---------------------------------------------------------------------------
__global__ __launch_bounds__(NTHR, 2)
void gemm_kernel(const float* __restrict__ Q,
                 const float* __restrict__ dist,
                 const float* __restrict__ W2,
                 const float* __restrict__ b2,
                 float* __restrict__ out) {
    extern __shared__ __align__(16) char dyn[];
    float*         As = (float*)dyn;                                  // STAGES x 128 x APAD
    __nv_bfloat16* Bs = (__nv_bfloat16*)(dyn + STAGES * A_STAGE_FLOATS * 4);
    float*         Ds = (float*)(dyn + STAGES * (A_STAGE_FLOATS * 4 + B_STAGE_HALFS * 2));

    __shared__ float s_w2[HID];
    __shared__ float s_rowsum[MT];
    __shared__ int   s_idx[MT];

    const int t = threadIdx.x, warp = t >> 5, lane = t & 31;
    const int m0 = blockIdx.x * MT;
    const uint32_t aSm = smem_u32(As);
    const uint32_t bSm = smem_u32(Bs);
    const uint32_t dSm = smem_u32(Ds);

    // loader mappings
    const int ar = t >> 1, ah = t & 1;            // A: 2 thr/row, 4x16B each
    const int dr = t >> 6, dc = t & 63;           // D: 64 thr/row, 2x16B each
    const float*         qrow = Q + (size_t)(m0 + ar) * EMBED;
    const __nv_bfloat16* brow = g_W1t + (size_t)ar * EMBED;
    const float*         dbase = dist + (size_t)m0 * NP;

    auto load_stage = [&](int c, int s) {
        const int k0 = c * KC;
        uint32_t aDst = aSm + s * (A_STAGE_FLOATS * 4) + ar * (APAD * 4);
        uint32_t bDst = bSm + s * (B_STAGE_HALFS * 2) + ar * (BPAD * 2);
        uint32_t dDst = dSm + s * (D_STAGE_FLOATS * 4) + dr * (NP * 4);
#pragma unroll
        for (int j = 0; j < 4; j++)
            cp_async16(aDst + (ah * 4 + j) * 16, qrow + k0 + (ah * 4 + j) * 4);
#pragma unroll
        for (int j = 0; j < 2; j++)
            cp_async16(bDst + (ah * 2 + j) * 16, brow + k0 + (ah * 2 + j) * 8);
        const float* dRow = dbase + (size_t)(c * 4 + dr) * NP;
#pragma unroll
        for (int j = 0; j < 2; j++)
            cp_async16(dDst + (dc * 2 + j) * 16, dRow + (dc * 2 + j) * 4);
    };

    if (t < HID) s_w2[t] = W2[t];
    if (t < MT)  s_rowsum[t] = 0.f;

    // ---- pipeline prologue ----
    load_stage(0, 0); CP_COMMIT();
    load_stage(1, 1); CP_COMMIT();

    // ---- accumulators + fragment mapping ----
    float acc[2][8][4];
#pragma unroll
    for (int mi = 0; mi < 2; mi++)
#pragma unroll
        for (int ni = 0; ni < 8; ni++)
#pragma unroll
            for (int r = 0; r < 4; r++) acc[mi][ni][r] = 0.f;

    const int warpM = warp >> 1;   // rows warpM*32
    const int warpN = warp & 1;    // cols warpN*64
    const int g  = lane >> 2;      // 0..7
    const int qd = lane & 3;       // 0..3

    // ---- mainloop ----
    for (int c = 0; c < NITER; c++) {
        const int sc = c % STAGES;
        CP_WAIT1();                 // stage c landed (c+1 may be in flight)
        __syncthreads();

        if (c + 2 < NITER) load_stage(c + 2, (c + 2) % STAGES);
        CP_COMMIT();

        const float*         A0 = As + sc * A_STAGE_FLOATS;
        const __nv_bfloat16* B0 = Bs + sc * B_STAGE_HALFS;

#pragma unroll
        for (int ks = 0; ks < 2; ks++) {
            const int ko = ks * 16;
            uint32_t a[2][4];
#pragma unroll
            for (int mi = 0; mi < 2; mi++) {
                const float* p1 = A0 + (warpM * 32 + mi * 16 + g) * APAD + ko + qd * 2;
                const float* p2 = p1 + 8 * APAD;
                float2 v;
                v = *(const float2*)(p1);     a[mi][0] = cvt_bf2(v.y, v.x);
                v = *(const float2*)(p2);     a[mi][1] = cvt_bf2(v.y, v.x);
                v = *(const float2*)(p1 + 8); a[mi][2] = cvt_bf2(v.y, v.x);
                v = *(const float2*)(p2 + 8); a[mi][3] = cvt_bf2(v.y, v.x);
            }
            uint32_t b[8][2];
#pragma unroll
            for (int ni = 0; ni < 8; ni++) {
                const __nv_bfloat16* pb = B0 + (warpN * 64 + ni * 8 + g) * BPAD + ko + qd * 2;
                b[ni][0] = *(const uint32_t*)(pb);
                b[ni][1] = *(const uint32_t*)(pb + 8);
            }
#pragma unroll
            for (int mi = 0; mi < 2; mi++)
#pragma unroll
                for (int ni = 0; ni < 8; ni++)
                    asm volatile(
                        "mma.sync.aligned.m16n8k16.row.col.f32.bf16.bf16.f32 "
                        "{%0,%1,%2,%3}, {%4,%5,%6,%7}, {%8,%9}, {%0,%1,%2,%3};\n"
                        : "+f"(acc[mi][ni][0]), "+f"(acc[mi][ni][1]),
                          "+f"(acc[mi][ni][2]), "+f"(acc[mi][ni][3])
                        : "r"(a[mi][0]), "r"(a[mi][1]), "r"(a[mi][2]), "r"(a[mi][3]),
                          "r"(b[ni][0]), "r"(b[ni][1]));
        }

        // ---- argmin fold from smem: warps 0-3 each fold one of this
        //      stage's 4 dist rows (LDS, conflict-free, latency-trivial) ----
        if (warp < 4) {
            const float* drow = Ds + sc * D_STAGE_FLOATS + warp * NP;
            float best = 3.4e38f; int bi = 0;
#pragma unroll
            for (int it = 0; it < 4; it++) {
                int j = it * 128 + lane * 4;
                float4 v = *(const float4*)(drow + j);
                if (v.x < best) { best = v.x; bi = j; }
                if (v.y < best) { best = v.y; bi = j + 1; }
                if (v.z < best) { best = v.z; bi = j + 2; }
                if (v.w < best) { best = v.w; bi = j + 3; }
            }
#pragma unroll
            for (int off = 16; off; off >>= 1) {
                float ov = __shfl_down_sync(0xffffffffu, best, off);
                int   oi = __shfl_down_sync(0xffffffffu, bi,   off);
                if (ov < best || (ov == best && oi < bi)) { best = ov; bi = oi; }
            }
            if (lane == 0) s_idx[c * 4 + warp] = bi;
        }
    }
    __syncthreads();    // all s_idx / folds complete

    // ---- epilogue: +Pb[idx], relu, * W2, row-reduce, sigmoid ----
#pragma unroll
    for (int mi = 0; mi < 2; mi++) {
#pragma unroll
        for (int rr = 0; rr < 2; rr++) {
            int rloc = warpM * 32 + mi * 16 + rr * 8 + g;
            const float* Pr = g_Pb + (size_t)s_idx[rloc] * HID;
            float s = 0.f;
#pragma unroll
            for (int ni = 0; ni < 8; ni++) {
                int cc = warpN * 64 + ni * 8 + qd * 2;
                float v0 = acc[mi][ni][rr * 2 + 0] + Pr[cc];
                float v1 = acc[mi][ni][rr * 2 + 1] + Pr[cc + 1];
                s += fmaxf(v0, 0.f) * s_w2[cc] + fmaxf(v1, 0.f) * s_w2[cc + 1];
            }
            atomicAdd(&s_rowsum[rloc], s);
        }
    }
    __syncthreads();
    if (t < MT) {
        float z = s_rowsum[t] + b2[0];
        out[m0 + t] = 1.f / (1.f + __expf(-z));
    }
}

// ---------------------------------------------------------------------------
extern "C" void kernel_launch(void* const* d_in, const int* in_sizes, int n_in,
                              void* d_out, int out_size) {
    const float* Q     = (const float*)d_in[0];   // [65536,1024]
    const float* proto = (const float*)d_in[1];   // [512,1024]
    const float* dist  = (const float*)d_in[2];   // [65536,512]
    const float* W1    = (const float*)d_in[3];   // [2048,128]
    const float* b1    = (const float*)d_in[4];   // [128]
    const float* W2    = (const float*)d_in[5];   // [128,1]
    const float* b2    = (const float*)d_in[6];   // [1]
    float* out = (float*)d_out;                   // [65536]

    static bool attr_set = false;
    if (!attr_set) {
        cudaFuncSetAttribute(gemm_kernel,
                             cudaFuncAttributeMaxDynamicSharedMemorySize, DYN_SMEM);
        attr_set = true;
    }

    w1t_kernel<<<dim3(EMBED / 32, HID / 32), dim3(32, 8)>>>(W1);
    proto_kernel<<<NP / 4, 256>>>(proto, W1, b1);
    gemm_kernel<<<NQ / MT, NTHR, DYN_SMEM>>>(Q, dist, W2, b2, out);
}

// round 15
// speedup vs baseline: 1.3018x; 1.1924x over previous
#include <cuda_runtime.h>
#include <cuda_bf16.h>
#include <cstdint>

#define EMBED 1024
#define HID   128
#define NQ    65536
#define NP    512
#define MT    128          // M rows per CTA
#define KC    32           // K elems per pipeline stage
#define NITER (EMBED / KC) // 32
#define STAGES 3
#define NTHR  256
#define APAD 36            // fp32 per A smem row (144B stride)
#define BPAD 40            // bf16 per B smem row (80B stride)
#define A_STAGE_FLOATS (MT * APAD)        // 4608 fp32 = 18432 B
#define B_STAGE_HALFS  (HID * BPAD)       // 5120 bf16 = 10240 B
#define DYN_SMEM (STAGES * (A_STAGE_FLOATS * 4 + B_STAGE_HALFS * 2))  // 86016 B

// Scratch: W1 top half transposed to bf16 [n][k]; Pb = proto @ W1_bot + b1.
__device__ __align__(16) __nv_bfloat16 g_W1t[HID * EMBED];
__device__ __align__(16) float g_Pb[NP * HID];

// ---------------------------------------------------------------------------
__device__ __forceinline__ uint32_t smem_u32(const void* p) {
    uint32_t a;
    asm("{ .reg .u64 t; cvta.to.shared.u64 t, %1; cvt.u32.u64 %0, t; }" : "=r"(a) : "l"(p));
    return a;
}
__device__ __forceinline__ void cp_async16(uint32_t dst, const void* src) {
    asm volatile("cp.async.cg.shared.global [%0], [%1], 16;" :: "r"(dst), "l"(src) : "memory");
}
#define CP_COMMIT() asm volatile("cp.async.commit_group;" ::: "memory")
#define CP_WAIT1()  asm volatile("cp.async.wait_group 1;" ::: "memory")

__device__ __forceinline__ uint32_t cvt_bf2(float hi, float lo) {
    uint32_t r;
    asm("cvt.rn.bf16x2.f32 %0, %1, %2;" : "=r"(r) : "f"(hi), "f"(lo));
    return r;
}

// ---------------------------------------------------------------------------
// Kernel 1: coalesced tile transpose W1_top (fp32 [k][n]) -> g_W1t (bf16 [n][k])
// ---------------------------------------------------------------------------
__global__ void w1t_kernel(const float* __restrict__ W1) {
    __shared__ float tile[32][33];
    int kb = blockIdx.x * 32, nb = blockIdx.y * 32;
    int tx = threadIdx.x, ty = threadIdx.y;
#pragma unroll
    for (int r = ty; r < 32; r += 8)
        tile[r][tx] = W1[(size_t)(kb + r) * HID + nb + tx];
    __syncthreads();
#pragma unroll
    for (int r = ty; r < 32; r += 8)
        g_W1t[(size_t)(nb + r) * EMBED + kb + tx] = __float2bfloat16(tile[tx][r]);
}

// ---------------------------------------------------------------------------
// Kernel 2: Pb[p][j] = proto[p] @ W1_bottom[:, j] + b1[j]
// cp.async staged, 3-buffer pipeline. 64 CTAs x 256 thr, 8 protos/CTA.
// ---------------------------------------------------------------------------
#define PKC 32
#define PNI (EMBED / PKC)   // 32
__global__ __launch_bounds__(256)
void proto_kernel(const float* __restrict__ proto,
                  const float* __restrict__ W1,
                  const float* __restrict__ b1) {
    __shared__ __align__(16) float sW[3][PKC][132];   // k x j, pad 132
    __shared__ __align__(16) float sP[3][8][36];      // p x k, pad 36

    const int t = threadIdx.x;
    const int j = t & 127;          // hid col
    const int pg = t >> 7;          // 0..1 -> protos pg*4 .. pg*4+3
    const int p0 = blockIdx.x * 8;

    const uint32_t wSm = smem_u32(sW);
    const uint32_t pSm = smem_u32(sP);

    // loader mapping: W chunk = 32 rows x 128 floats = 1024 float4; 4/thread
    auto load_stage = [&](int kc, int s) {
        const int k0 = kc * PKC;
#pragma unroll
        for (int r = 0; r < 4; r++) {
            int slot = t + r * 256;              // 0..1023
            int row = slot >> 5, col = (slot & 31) * 4;
            cp_async16(wSm + (uint32_t)(s * (PKC * 132) + row * 132 + col) * 4,
                       W1 + (size_t)(EMBED + k0 + row) * HID + col);
        }
        if (t < 64) {                            // P chunk = 8 x 32 = 64 float4
            int row = t >> 3, col = (t & 7) * 4;
            cp_async16(pSm + (uint32_t)(s * (8 * 36) + row * 36 + col) * 4,
                       proto + (size_t)(p0 + row) * EMBED + k0 + col);
        }
    };

    load_stage(0, 0); CP_COMMIT();
    load_stage(1, 1); CP_COMMIT();

    float acc0 = 0.f, acc1 = 0.f, acc2 = 0.f, acc3 = 0.f;

    for (int kc = 0; kc < PNI; kc++) {
        const int sc = kc % 3;
        CP_WAIT1();
        __syncthreads();
        if (kc + 2 < PNI) load_stage(kc + 2, (kc + 2) % 3);
        CP_COMMIT();

        const float (*W)[132] = sW[sc];
        const float (*P)[36]  = sP[sc];
#pragma unroll
        for (int k = 0; k < PKC; k++) {
            float w = W[k][j];
            acc0 += P[pg * 4 + 0][k] * w;
            acc1 += P[pg * 4 + 1][k] * w;
            acc2 += P[pg * 4 + 2][k] * w;
            acc3 += P[pg * 4 + 3][k] * w;
        }
        __syncthreads();
    }
    float bb = b1[j];
    g_Pb[(size_t)(p0 + pg * 4 + 0) * HID + j] = acc0 + bb;
    g_Pb[(size_t)(p0 + pg * 4 + 1) * HID + j] = acc1 + bb;
    g_Pb[(size_t)(p0 + pg * 4 + 2) * HID + j] = acc2 + bb;
    g_Pb[(size_t)(p0 + pg * 4 + 3) * HID + j] = acc3 + bb;
}

// ---------------------------------------------------------------------------
// Kernel 3: fused argmin prologue + pipelined bf16 mma.sync GEMM + epilogue.
// 256 threads (8 warps 4Mx2N, warp tile 32x64), 3 stages (A+B only, 86KB),
// 2 CTAs/SM. NO fragment staging arrays -> ~100 regs, zero spills.
// ---------------------------------------------------------------------------
__global__ __launch_bounds__(NTHR, 2)
void gemm_kernel(const float* __restrict__ Q,
                 const float* __restrict__ dist,
                 const float* __restrict__ W2,
                 const float* __restrict__ b2,
                 float* __restrict__ out) {
    extern __shared__ __align__(16) char dyn[];
    float*         As = (float*)dyn;                                  // 3 x 128 x APAD
    __nv_bfloat16* Bs = (__nv_bfloat16*)(dyn + STAGES * A_STAGE_FLOATS * 4);

    __shared__ float s_w2[HID];
    __shared__ float s_rowsum[MT];
    __shared__ int   s_idx[MT];

    const int t = threadIdx.x, warp = t >> 5, lane = t & 31;
    const int m0 = blockIdx.x * MT;
    const uint32_t aSm = smem_u32(As);
    const uint32_t bSm = smem_u32(Bs);

    // loader mapping: 2 threads/row
    const int lr = t >> 1, lh = t & 1;
    const float*         qrow = Q + (size_t)(m0 + lr) * EMBED;
    const __nv_bfloat16* brow = g_W1t + (size_t)lr * EMBED;

    auto load_stage = [&](int c, int s) {
        const int k0 = c * KC;
        uint32_t aDst = aSm + s * (A_STAGE_FLOATS * 4) + lr * (APAD * 4);
        uint32_t bDst = bSm + s * (B_STAGE_HALFS * 2) + lr * (BPAD * 2);
#pragma unroll
        for (int jj = 0; jj < 4; jj++)
            cp_async16(aDst + (lh * 4 + jj) * 16, qrow + k0 + (lh * 4 + jj) * 4);
#pragma unroll
        for (int jj = 0; jj < 2; jj++)
            cp_async16(bDst + (lh * 2 + jj) * 16, brow + k0 + (lh * 2 + jj) * 8);
    };

    // ---- start the pipeline BEFORE argmin so Q loads land under it ----
    load_stage(0, 0); CP_COMMIT();
    load_stage(1, 1); CP_COMMIT();

    if (t < HID) s_w2[t] = W2[t];
    if (t < MT)  s_rowsum[t] = 0.f;

    // ---- argmin prologue: warp w handles rows w, w+8, ..., w+120 ----
    for (int i = 0; i < 16; i++) {
        int qi = warp + i * 8;
        const float* row = dist + (size_t)(m0 + qi) * NP;
        float best = 3.4e38f; int bi = 0;
#pragma unroll
        for (int it = 0; it < 4; it++) {
            int jj = it * 128 + lane * 4;
            float4 v = *(const float4*)(row + jj);
            if (v.x < best) { best = v.x; bi = jj; }
            if (v.y < best) { best = v.y; bi = jj + 1; }
            if (v.z < best) { best = v.z; bi = jj + 2; }
            if (v.w < best) { best = v.w; bi = jj + 3; }
        }
#pragma unroll
        for (int off = 16; off; off >>= 1) {
            float ov = __shfl_down_sync(0xffffffffu, best, off);
            int   oi = __shfl_down_sync(0xffffffffu, bi,   off);
            if (ov < best || (ov == best && oi < bi)) { best = ov; bi = oi; }
        }
        if (lane == 0) s_idx[qi] = bi;
    }

    // ---- accumulators + fragment mapping ----
    float acc[2][8][4];
#pragma unroll
    for (int mi = 0; mi < 2; mi++)
#pragma unroll
        for (int ni = 0; ni < 8; ni++)
#pragma unroll
            for (int r = 0; r < 4; r++) acc[mi][ni][r] = 0.f;

    const int warpM = warp >> 1;   // rows warpM*32
    const int warpN = warp & 1;    // cols warpN*64
    const int g  = lane >> 2;      // 0..7
    const int qd = lane & 3;       // 0..3

    // ---- mainloop: no staging arrays, minimal live registers ----
    for (int c = 0; c < NITER; c++) {
        const int sc = c % STAGES;
        CP_WAIT1();
        __syncthreads();

        if (c + 2 < NITER) load_stage(c + 2, (c + 2) % STAGES);
        CP_COMMIT();

        const float*         A0 = As + sc * A_STAGE_FLOATS;
        const __nv_bfloat16* B0 = Bs + sc * B_STAGE_HALFS;

#pragma unroll
        for (int ks = 0; ks < 2; ks++) {
            const int ko = ks * 16;
#pragma unroll
            for (int mi = 0; mi < 2; mi++) {
                const float* p1 = A0 + (warpM * 32 + mi * 16 + g) * APAD + ko + qd * 2;
                const float* p2 = p1 + 8 * APAD;
                float2 v;
                uint32_t a0, a1, a2, a3;
                v = *(const float2*)(p1);     a0 = cvt_bf2(v.y, v.x);
                v = *(const float2*)(p2);     a1 = cvt_bf2(v.y, v.x);
                v = *(const float2*)(p1 + 8); a2 = cvt_bf2(v.y, v.x);
                v = *(const float2*)(p2 + 8); a3 = cvt_bf2(v.y, v.x);
                const __nv_bfloat16* pb0 = B0 + (warpN * 64 + g) * BPAD + ko + qd * 2;
#pragma unroll
                for (int ni = 0; ni < 8; ni++) {
                    uint32_t b0 = *(const uint32_t*)(pb0 + ni * 8 * BPAD);
                    uint32_t b1 = *(const uint32_t*)(pb0 + ni * 8 * BPAD + 8);
                    asm volatile(
                        "mma.sync.aligned.m16n8k16.row.col.f32.bf16.bf16.f32 "
                        "{%0,%1,%2,%3}, {%4,%5,%6,%7}, {%8,%9}, {%0,%1,%2,%3};\n"
                        : "+f"(acc[mi][ni][0]), "+f"(acc[mi][ni][1]),
                          "+f"(acc[mi][ni][2]), "+f"(acc[mi][ni][3])
                        : "r"(a0), "r"(a1), "r"(a2), "r"(a3), "r"(b0), "r"(b1));
                }
            }
        }
    }

    // ---- epilogue: +Pb[idx], relu, * W2, quad-reduce, atomic, sigmoid ----
#pragma unroll
    for (int mi = 0; mi < 2; mi++) {
#pragma unroll
        for (int rr = 0; rr < 2; rr++) {
            int rloc = warpM * 32 + mi * 16 + rr * 8 + g;
            const float* Pr = g_Pb + (size_t)s_idx[rloc] * HID;
            float s = 0.f;
#pragma unroll
            for (int ni = 0; ni < 8; ni++) {
                int cc = warpN * 64 + ni * 8 + qd * 2;
                float v0 = acc[mi][ni][rr * 2 + 0] + Pr[cc];
                float v1 = acc[mi][ni][rr * 2 + 1] + Pr[cc + 1];
                s += fmaxf(v0, 0.f) * s_w2[cc] + fmaxf(v1, 0.f) * s_w2[cc + 1];
            }
            s += __shfl_xor_sync(0xffffffffu, s, 1);
            s += __shfl_xor_sync(0xffffffffu, s, 2);
            if (qd == 0) atomicAdd(&s_rowsum[rloc], s);
        }
    }
    __syncthreads();
    if (t < MT) {
        float z = s_rowsum[t] + b2[0];
        out[m0 + t] = 1.f / (1.f + __expf(-z));
    }
}

// ---------------------------------------------------------------------------
extern "C" void kernel_launch(void* const* d_in, const int* in_sizes, int n_in,
                              void* d_out, int out_size) {
    const float* Q     = (const float*)d_in[0];   // [65536,1024]
    const float* proto = (const float*)d_in[1];   // [512,1024]
    const float* dist  = (const float*)d_in[2];   // [65536,512]
    const float* W1    = (const float*)d_in[3];   // [2048,128]
    const float* b1    = (const float*)d_in[4];   // [128]
    const float* W2    = (const float*)d_in[5];   // [128,1]
    const float* b2    = (const float*)d_in[6];   // [1]
    float* out = (float*)d_out;                   // [65536]

    static bool attr_set = false;
    if (!attr_set) {
        cudaFuncSetAttribute(gemm_kernel,
                             cudaFuncAttributeMaxDynamicSharedMemorySize, DYN_SMEM);
        attr_set = true;
    }

    w1t_kernel<<<dim3(EMBED / 32, HID / 32), dim3(32, 8)>>>(W1);
    proto_kernel<<<NP / 8, 256>>>(proto, W1, b1);
    gemm_kernel<<<NQ / MT, NTHR, DYN_SMEM>>>(Q, dist, W2, b2, out);
}

// round 16
// speedup vs baseline: 2.0151x; 1.5478x over previous
#include <cuda_runtime.h>
#include <cuda.h>
#include <cuda_bf16.h>
#include <cstdint>

#define EMBED 1024
#define HID   128
#define NQ    65536
#define NP    512
#define MT    128          // M rows per CTA
#define KC    32           // K elems per stage
#define NITER (EMBED / KC) // 32
#define STAGES 3
#define NTHR  256
#define BPAD  40           // bf16 per B row (80B stride, conflict-free)
#define A_ST_BYTES (MT * KC * 4)        // 16384 (SW128-swizzled by TMA)
#define B_ST_BYTES (HID * BPAD * 2)     // 10240 (contiguous, pad baked in)
#define D_ST_BYTES (4 * NP * 4)         //  8192 (4 dist rows)
#define STAGE_TX   (A_ST_BYTES + B_ST_BYTES + D_ST_BYTES)   // 34816
#define A_TOT (STAGES * A_ST_BYTES)
#define B_TOT (STAGES * B_ST_BYTES)
#define D_TOT (STAGES * D_ST_BYTES)
#define DYN_SMEM (A_TOT + B_TOT + D_TOT + 1024)             // 105472 -> 2 CTAs/SM

// Scratch: W1 top half, bf16, CHUNK-MAJOR PADDED: [chunk c][n][BPAD] so each
// stage's B tile is one contiguous 10240B bulk copy. Pb = proto @ W1_bot + b1.
__device__ __align__(16) __nv_bfloat16 g_W1t[NITER * HID * BPAD];
__device__ __align__(16) float g_Pb[NP * HID];

// ---------------------------------------------------------------------------
__device__ __forceinline__ uint32_t smem_u32(const void* p) {
    uint32_t a;
    asm("{ .reg .u64 t; cvta.to.shared.u64 t, %1; cvt.u32.u64 %0, t; }" : "=r"(a) : "l"(p));
    return a;
}
__device__ __forceinline__ uint32_t cvt_bf2(float hi, float lo) {
    uint32_t r;
    asm("cvt.rn.bf16x2.f32 %0, %1, %2;" : "=r"(r) : "f"(hi), "f"(lo));
    return r;
}
#define MBAR_INIT(a, c) asm volatile("mbarrier.init.shared.b64 [%0], %1;" :: "r"(a), "r"(c) : "memory")
#define MBAR_EXPECT_TX(a, n) asm volatile("mbarrier.arrive.expect_tx.shared.b64 _, [%0], %1;" :: "r"(a), "r"((uint32_t)(n)) : "memory")
#define MBAR_WAIT(a, ph) do {                                                           \
    uint32_t _m = (a), _p = (ph), _d;                                                   \
    asm volatile("{\n\t.reg .pred p;\n\t"                                               \
        "mbarrier.try_wait.parity.acquire.cta.shared::cta.b64 p, [%1], %2;\n\t"         \
        "selp.b32 %0, 1, 0, p;\n\t}" : "=r"(_d) : "r"(_m), "r"(_p) : "memory");         \
    if (!_d) {                                                                          \
        asm volatile("{\n\t.reg .pred P1;\n\t"                                          \
            "WL_%=:\n\t"                                                                \
            "mbarrier.try_wait.parity.acquire.cta.shared::cta.b64 P1, [%0], %1, 0x989680;\n\t" \
            "@P1 bra.uni WD_%=;\n\t"                                                    \
            "bra.uni WL_%=;\n\t"                                                        \
            "WD_%=:\n\t}" :: "r"(_m), "r"(_p) : "memory");                              \
    }                                                                                   \
} while (0)
#define FENCE_ASYNC() asm volatile("fence.proxy.async.shared::cta;" ::: "memory")

__device__ __forceinline__ void tma_tile_2d(uint32_t dst, const void* tmap,
                                            int x, int y, uint32_t bar) {
    asm volatile(
        "cp.async.bulk.tensor.2d.shared::cluster.global.tile.mbarrier::complete_tx::bytes "
        "[%0], [%1, {%2, %3}], [%4];"
        :: "r"(dst), "l"(tmap), "r"(x), "r"(y), "r"(bar) : "memory");
}
__device__ __forceinline__ void bulk_1d(uint32_t dst, const void* src,
                                        uint32_t bytes, uint32_t bar) {
    asm volatile(
        "cp.async.bulk.shared::cluster.global.mbarrier::complete_tx::bytes "
        "[%0], [%1], %2, [%3];"
        :: "r"(dst), "l"(src), "r"(bytes), "r"(bar) : "memory");
}

// ---------------------------------------------------------------------------
// Kernel 1: transpose W1_top (fp32 [k][n]) -> g_W1t chunk-major padded bf16.
// grid (32, 4), block (32, 8): blockIdx.x IS the k-chunk.
// ---------------------------------------------------------------------------
__global__ void w1t_kernel(const float* __restrict__ W1) {
    __shared__ float tile[32][33];
    int kb = blockIdx.x * 32, nb = blockIdx.y * 32;
    int tx = threadIdx.x, ty = threadIdx.y;
#pragma unroll
    for (int r = ty; r < 32; r += 8)
        tile[r][tx] = W1[(size_t)(kb + r) * HID + nb + tx];
    __syncthreads();
#pragma unroll
    for (int r = ty; r < 32; r += 8)
        g_W1t[(size_t)blockIdx.x * (HID * BPAD) + (nb + r) * BPAD + tx] =
            __float2bfloat16(tile[tx][r]);
}

// ---------------------------------------------------------------------------
// Kernel 2: Pb[p][j] = proto[p] @ W1_bottom[:, j] + b1[j]  (R15 version)
// ---------------------------------------------------------------------------
__device__ __forceinline__ void cp_async16(uint32_t dst, const void* src) {
    asm volatile("cp.async.cg.shared.global [%0], [%1], 16;" :: "r"(dst), "l"(src) : "memory");
}
#define CP_COMMIT() asm volatile("cp.async.commit_group;" ::: "memory")
#define CP_WAIT1()  asm volatile("cp.async.wait_group 1;" ::: "memory")

#define PKC 32
#define PNI (EMBED / PKC)
__global__ __launch_bounds__(256)
void proto_kernel(const float* __restrict__ proto,
                  const float* __restrict__ W1,
                  const float* __restrict__ b1) {
    __shared__ __align__(16) float sW[3][PKC][132];
    __shared__ __align__(16) float sP[3][8][36];

    const int t = threadIdx.x;
    const int j = t & 127;
    const int pg = t >> 7;
    const int p0 = blockIdx.x * 8;

    const uint32_t wSm = smem_u32(sW);
    const uint32_t pSm = smem_u32(sP);

    auto load_stage = [&](int kc, int s) {
        const int k0 = kc * PKC;
#pragma unroll
        for (int r = 0; r < 4; r++) {
            int slot = t + r * 256;
            int row = slot >> 5, col = (slot & 31) * 4;
            cp_async16(wSm + (uint32_t)(s * (PKC * 132) + row * 132 + col) * 4,
                       W1 + (size_t)(EMBED + k0 + row) * HID + col);
        }
        if (t < 64) {
            int row = t >> 3, col = (t & 7) * 4;
            cp_async16(pSm + (uint32_t)(s * (8 * 36) + row * 36 + col) * 4,
                       proto + (size_t)(p0 + row) * EMBED + k0 + col);
        }
    };

    load_stage(0, 0); CP_COMMIT();
    load_stage(1, 1); CP_COMMIT();

    float acc0 = 0.f, acc1 = 0.f, acc2 = 0.f, acc3 = 0.f;
    for (int kc = 0; kc < PNI; kc++) {
        const int sc = kc % 3;
        CP_WAIT1();
        __syncthreads();
        if (kc + 2 < PNI) load_stage(kc + 2, (kc + 2) % 3);
        CP_COMMIT();
        const float (*W)[132] = sW[sc];
        const float (*P)[36]  = sP[sc];
#pragma unroll
        for (int k = 0; k < PKC; k++) {
            float w = W[k][j];
            acc0 += P[pg * 4 + 0][k] * w;
            acc1 += P[pg * 4 + 1][k] * w;
            acc2 += P[pg * 4 + 2][k] * w;
            acc3 += P[pg * 4 + 3][k] * w;
        }
        __syncthreads();
    }
    float bb = b1[j];
    g_Pb[(size_t)(p0 + pg * 4 + 0) * HID + j] = acc0 + bb;
    g_Pb[(size_t)(p0 + pg * 4 + 1) * HID + j] = acc1 + bb;
    g_Pb[(size_t)(p0 + pg * 4 + 2) * HID + j] = acc2 + bb;
    g_Pb[(size_t)(p0 + pg * 4 + 3) * HID + j] = acc3 + bb;
}

// ---------------------------------------------------------------------------
// Kernel 3: TMA-fed pipeline. Per stage: one 2D TMA tile (A, SW128), one 1D
// bulk (B), one 1D bulk (4 dist rows). 3 requests/stage vs 1536 cp.asyncs.
// Argmin folds in-loop from smem. bf16 mma.sync GEMM + fused MLP epilogue.
// 256 threads (8 warps 4Mx2N), 3 stages, 2 CTAs/SM.
// ---------------------------------------------------------------------------
__global__ __launch_bounds__(NTHR, 2)
void gemm_kernel(const __grid_constant__ CUtensorMap tmapA,
                 const float* __restrict__ dist,
                 const float* __restrict__ W2,
                 const float* __restrict__ b2,
                 float* __restrict__ out) {
    extern __shared__ __align__(16) char dyn_raw[];
    __shared__ __align__(8) uint64_t s_full[STAGES];
    __shared__ float s_w2[HID];
    __shared__ float s_rowsum[MT];
    __shared__ int   s_idx[MT];

    const int t = threadIdx.x, warp = t >> 5, lane = t & 31;
    const int m0 = blockIdx.x * MT;

    const uint32_t base_raw = smem_u32(dyn_raw);
    const uint32_t base = (base_raw + 1023u) & ~1023u;   // SW128 atom alignment
    char* dynA = dyn_raw + (base - base_raw);
    const uint32_t barBase = smem_u32(s_full);

    if (t == 0) {
#pragma unroll
        for (int s = 0; s < STAGES; s++) MBAR_INIT(barBase + s * 8, 1);
        FENCE_ASYNC();
    }
    if (t < HID) s_w2[t] = W2[t];
    if (t < MT)  s_rowsum[t] = 0.f;
    __syncthreads();

    auto issue = [&](int c) {                      // thread 0 only
        const int s = c % STAGES;
        const uint32_t bar = barBase + s * 8;
        MBAR_EXPECT_TX(bar, STAGE_TX);
        tma_tile_2d(base + s * A_ST_BYTES, (const void*)&tmapA, c * KC, m0, bar);
        bulk_1d(base + A_TOT + s * B_ST_BYTES,
                g_W1t + (size_t)c * (HID * BPAD), B_ST_BYTES, bar);
        bulk_1d(base + A_TOT + B_TOT + s * D_ST_BYTES,
                dist + (size_t)(m0 + c * 4) * NP, D_ST_BYTES, bar);
    };

    if (t == 0) { issue(0); issue(1); }

    // ---- accumulators + fragment mapping ----
    float acc[2][8][4];
#pragma unroll
    for (int mi = 0; mi < 2; mi++)
#pragma unroll
        for (int ni = 0; ni < 8; ni++)
#pragma unroll
            for (int r = 0; r < 4; r++) acc[mi][ni][r] = 0.f;

    const int warpM = warp >> 1;   // rows warpM*32
    const int warpN = warp & 1;    // cols warpN*64
    const int g  = lane >> 2;      // 0..7
    const int qd = lane & 3;       // 0..3
    const int gx = g * 4;          // SW128 xor term (bytes>>2) for this thread

    for (int c = 0; c < NITER; c++) {
        const int sc = c % STAGES;
        if (t == 0 && c + 2 < NITER) issue(c + 2);   // slot (c+2)%3 freed by prev-iter sync
        MBAR_WAIT(barBase + sc * 8, (c / STAGES) & 1);

        const float*         A0 = (const float*)(dynA + sc * A_ST_BYTES);
        const __nv_bfloat16* B0 = (const __nv_bfloat16*)(dynA + A_TOT + sc * B_ST_BYTES);
        const float*         D0 = (const float*)(dynA + A_TOT + B_TOT + sc * D_ST_BYTES);

#pragma unroll
        for (int ks = 0; ks < 2; ks++) {
            const int ko = ks * 16;
            const int col0 = (ko + qd * 2) ^ gx;       // SW128: physical = logical ^ (g*16B)
            const int col2 = (ko + qd * 2 + 8) ^ gx;
#pragma unroll
            for (int mi = 0; mi < 2; mi++) {
                const float* r1 = A0 + (warpM * 32 + mi * 16 + g) * 32;
                const float* r2 = r1 + 8 * 32;
                float2 v;
                uint32_t a0, a1, a2, a3;
                v = *(const float2*)(r1 + col0); a0 = cvt_bf2(v.y, v.x);
                v = *(const float2*)(r2 + col0); a1 = cvt_bf2(v.y, v.x);
                v = *(const float2*)(r1 + col2); a2 = cvt_bf2(v.y, v.x);
                v = *(const float2*)(r2 + col2); a3 = cvt_bf2(v.y, v.x);
                const __nv_bfloat16* pb0 = B0 + (warpN * 64 + g) * BPAD + ko + qd * 2;
#pragma unroll
                for (int ni = 0; ni < 8; ni++) {
                    uint32_t b0 = *(const uint32_t*)(pb0 + ni * 8 * BPAD);
                    uint32_t b1 = *(const uint32_t*)(pb0 + ni * 8 * BPAD + 8);
                    asm volatile(
                        "mma.sync.aligned.m16n8k16.row.col.f32.bf16.bf16.f32 "
                        "{%0,%1,%2,%3}, {%4,%5,%6,%7}, {%8,%9}, {%0,%1,%2,%3};\n"
                        : "+f"(acc[mi][ni][0]), "+f"(acc[mi][ni][1]),
                          "+f"(acc[mi][ni][2]), "+f"(acc[mi][ni][3])
                        : "r"(a0), "r"(a1), "r"(a2), "r"(a3), "r"(b0), "r"(b1));
                }
            }
        }

        // ---- argmin fold: warps 0-3 each fold one of this stage's 4 rows ----
        if (warp < 4) {
            const float* drow = D0 + warp * NP;
            float best = 3.4e38f; int bi = 0;
#pragma unroll
            for (int it = 0; it < 4; it++) {
                int jj = it * 128 + lane * 4;
                float4 v = *(const float4*)(drow + jj);
                if (v.x < best) { best = v.x; bi = jj; }
                if (v.y < best) { best = v.y; bi = jj + 1; }
                if (v.z < best) { best = v.z; bi = jj + 2; }
                if (v.w < best) { best = v.w; bi = jj + 3; }
            }
#pragma unroll
            for (int off = 16; off; off >>= 1) {
                float ov = __shfl_down_sync(0xffffffffu, best, off);
                int   oi = __shfl_down_sync(0xffffffffu, bi,   off);
                if (ov < best || (ov == best && oi < bi)) { best = ov; bi = oi; }
            }
            if (lane == 0) s_idx[c * 4 + warp] = bi;
        }
        __syncthreads();    // everyone done with stage sc before it is re-issued
    }

    // ---- epilogue: +Pb[idx], relu, * W2, quad-reduce, atomic, sigmoid ----
#pragma unroll
    for (int mi = 0; mi < 2; mi++) {
#pragma unroll
        for (int rr = 0; rr < 2; rr++) {
            int rloc = warpM * 32 + mi * 16 + rr * 8 + g;
            const float* Pr = g_Pb + (size_t)s_idx[rloc] * HID;
            float s = 0.f;
#pragma unroll
            for (int ni = 0; ni < 8; ni++) {
                int cc = warpN * 64 + ni * 8 + qd * 2;
                float v0 = acc[mi][ni][rr * 2 + 0] + Pr[cc];
                float v1 = acc[mi][ni][rr * 2 + 1] + Pr[cc + 1];
                s += fmaxf(v0, 0.f) * s_w2[cc] + fmaxf(v1, 0.f) * s_w2[cc + 1];
            }
            s += __shfl_xor_sync(0xffffffffu, s, 1);
            s += __shfl_xor_sync(0xffffffffu, s, 2);
            if (qd == 0) atomicAdd(&s_rowsum[rloc], s);
        }
    }
    __syncthreads();
    if (t < MT) {
        float z = s_rowsum[t] + b2[0];
        out[m0 + t] = 1.f / (1.f + __expf(-z));
    }
}

// ---------------------------------------------------------------------------
typedef CUresult (CUDAAPI *EncodeFn)(
    CUtensorMap*, CUtensorMapDataType, cuuint32_t, void*,
    const cuuint64_t*, const cuuint64_t*, const cuuint32_t*, const cuuint32_t*,
    CUtensorMapInterleave, CUtensorMapSwizzle, CUtensorMapL2promotion,
    CUtensorMapFloatOOBfill);

extern "C" void kernel_launch(void* const* d_in, const int* in_sizes, int n_in,
                              void* d_out, int out_size) {
    const float* Q     = (const float*)d_in[0];   // [65536,1024]
    const float* proto = (const float*)d_in[1];   // [512,1024]
    const float* dist  = (const float*)d_in[2];   // [65536,512]
    const float* W1    = (const float*)d_in[3];   // [2048,128]
    const float* b1    = (const float*)d_in[4];   // [128]
    const float* W2    = (const float*)d_in[5];   // [128,1]
    const float* b2    = (const float*)d_in[6];   // [1]
    float* out = (float*)d_out;                   // [65536]

    static EncodeFn enc = nullptr;
    static bool attr_set = false;
    if (!attr_set) {
        cudaFuncSetAttribute(gemm_kernel,
                             cudaFuncAttributeMaxDynamicSharedMemorySize, DYN_SMEM);
        attr_set = true;
    }
    if (!enc) {
        cudaDriverEntryPointQueryResult qr;
#if CUDART_VERSION >= 12050
        cudaGetDriverEntryPointByVersion("cuTensorMapEncodeTiled", (void**)&enc,
                                         12000, cudaEnableDefault, &qr);
#endif
        if (!enc)
            cudaGetDriverEntryPoint("cuTensorMapEncodeTiled", (void**)&enc,
                                    cudaEnableDefault, &qr);
    }

    CUtensorMap tmapA;
    {
        cuuint64_t dims[2]    = {EMBED, NQ};
        cuuint64_t strides[1] = {EMBED * sizeof(float)};
        cuuint32_t box[2]     = {KC, MT};            // 32 fp32 = 128B = SW128 limit
        cuuint32_t estr[2]    = {1, 1};
        enc(&tmapA, CU_TENSOR_MAP_DATA_TYPE_FLOAT32, 2, (void*)Q,
            dims, strides, box, estr,
            CU_TENSOR_MAP_INTERLEAVE_NONE, CU_TENSOR_MAP_SWIZZLE_128B,
            CU_TENSOR_MAP_L2_PROMOTION_L2_128B, CU_TENSOR_MAP_FLOAT_OOB_FILL_NONE);
    }

    w1t_kernel<<<dim3(EMBED / 32, HID / 32), dim3(32, 8)>>>(W1);
    proto_kernel<<<NP / 8, 256>>>(proto, W1, b1);
    gemm_kernel<<<NQ / MT, NTHR, DYN_SMEM>>>(tmapA, dist, W2, b2, out);
}

// round 17
// speedup vs baseline: 2.0459x; 1.0153x over previous
#include <cuda_runtime.h>
#include <cuda.h>
#include <cuda_bf16.h>
#include <cstdint>

#define EMBED 1024
#define HID   128
#define NQ    65536
#define NP    512
#define MT    128          // M rows per CTA
#define KC    32           // K elems per stage
#define NITER (EMBED / KC) // 32
#define STAGES 3
#define NTHR  256
#define BPAD  40           // bf16 per B row (80B stride, conflict-free)
#define A_ST_BYTES (MT * KC * 4)        // 16384 (SW128-swizzled by TMA)
#define B_ST_BYTES (HID * BPAD * 2)     // 10240 (contiguous, pad baked in)
#define D_ST_BYTES (4 * NP * 4)         //  8192 (4 dist rows)
#define STAGE_TX   (A_ST_BYTES + B_ST_BYTES + D_ST_BYTES)   // 34816
#define A_TOT (STAGES * A_ST_BYTES)
#define B_TOT (STAGES * B_ST_BYTES)
#define D_TOT (STAGES * D_ST_BYTES)
#define DYN_SMEM (A_TOT + B_TOT + D_TOT + 1024)             // 105472 -> 2 CTAs/SM

// Scratch: W1 top half, bf16, CHUNK-MAJOR PADDED: [chunk c][n][BPAD] so each
// stage's B tile is one contiguous 10240B bulk copy. Pb = proto @ W1_bot + b1.
__device__ __align__(16) __nv_bfloat16 g_W1t[NITER * HID * BPAD];
__device__ __align__(16) float g_Pb[NP * HID];

// ---------------------------------------------------------------------------
__device__ __forceinline__ uint32_t smem_u32(const void* p) {
    uint32_t a;
    asm("{ .reg .u64 t; cvta.to.shared.u64 t, %1; cvt.u32.u64 %0, t; }" : "=r"(a) : "l"(p));
    return a;
}
__device__ __forceinline__ uint32_t cvt_bf2(float hi, float lo) {
    uint32_t r;
    asm("cvt.rn.bf16x2.f32 %0, %1, %2;" : "=r"(r) : "f"(hi), "f"(lo));
    return r;
}
__device__ __forceinline__ uint32_t elect_one() {
    uint32_t pred;
    asm volatile("{\n\t.reg .pred p;\n\telect.sync _|p, 0xFFFFFFFF;\n\tselp.b32 %0, 1, 0, p;\n\t}" : "=r"(pred));
    return pred;
}
#define MBAR_INIT(a, c) asm volatile("mbarrier.init.shared.b64 [%0], %1;" :: "r"(a), "r"(c) : "memory")
#define MBAR_EXPECT_TX(a, n) asm volatile("mbarrier.arrive.expect_tx.shared.b64 _, [%0], %1;" :: "r"(a), "r"((uint32_t)(n)) : "memory")
#define MBAR_WAIT(a, ph) do {                                                           \
    uint32_t _m = (a), _p = (ph), _d;                                                   \
    asm volatile("{\n\t.reg .pred p;\n\t"                                               \
        "mbarrier.try_wait.parity.acquire.cta.shared::cta.b64 p, [%1], %2;\n\t"         \
        "selp.b32 %0, 1, 0, p;\n\t}" : "=r"(_d) : "r"(_m), "r"(_p) : "memory");         \
    if (!_d) {                                                                          \
        asm volatile("{\n\t.reg .pred P1;\n\t"                                          \
            "WL_%=:\n\t"                                                                \
            "mbarrier.try_wait.parity.acquire.cta.shared::cta.b64 P1, [%0], %1, 0x989680;\n\t" \
            "@P1 bra.uni WD_%=;\n\t"                                                    \
            "bra.uni WL_%=;\n\t"                                                        \
            "WD_%=:\n\t}" :: "r"(_m), "r"(_p) : "memory");                              \
    }                                                                                   \
} while (0)
#define FENCE_ASYNC() asm volatile("fence.proxy.async.shared::cta;" ::: "memory")

__device__ __forceinline__ void tma_tile_2d(uint32_t dst, const void* tmap,
                                            int x, int y, uint32_t bar) {
    asm volatile(
        "cp.async.bulk.tensor.2d.shared::cluster.global.tile.mbarrier::complete_tx::bytes "
        "[%0], [%1, {%2, %3}], [%4];"
        :: "r"(dst), "l"(tmap), "r"(x), "r"(y), "r"(bar) : "memory");
}
__device__ __forceinline__ void bulk_1d(uint32_t dst, const void* src,
                                        uint32_t bytes, uint32_t bar) {
    asm volatile(
        "cp.async.bulk.shared::cluster.global.mbarrier::complete_tx::bytes "
        "[%0], [%1], %2, [%3];"
        :: "r"(dst), "l"(src), "r"(bytes), "r"(bar) : "memory");
}

// ---------------------------------------------------------------------------
// Kernel 1: transpose W1_top (fp32 [k][n]) -> g_W1t chunk-major padded bf16.
// ---------------------------------------------------------------------------
__global__ void w1t_kernel(const float* __restrict__ W1) {
    __shared__ float tile[32][33];
    int kb = blockIdx.x * 32, nb = blockIdx.y * 32;
    int tx = threadIdx.x, ty = threadIdx.y;
#pragma unroll
    for (int r = ty; r < 32; r += 8)
        tile[r][tx] = W1[(size_t)(kb + r) * HID + nb + tx];
    __syncthreads();
#pragma unroll
    for (int r = ty; r < 32; r += 8)
        g_W1t[(size_t)blockIdx.x * (HID * BPAD) + (nb + r) * BPAD + tx] =
            __float2bfloat16(tile[tx][r]);
}

// ---------------------------------------------------------------------------
// Kernel 2: Pb[p][j] = proto[p] @ W1_bottom[:, j] + b1[j]
// ---------------------------------------------------------------------------
__device__ __forceinline__ void cp_async16(uint32_t dst, const void* src) {
    asm volatile("cp.async.cg.shared.global [%0], [%1], 16;" :: "r"(dst), "l"(src) : "memory");
}
#define CP_COMMIT() asm volatile("cp.async.commit_group;" ::: "memory")
#define CP_WAIT1()  asm volatile("cp.async.wait_group 1;" ::: "memory")

#define PKC 32
#define PNI (EMBED / PKC)
__global__ __launch_bounds__(256)
void proto_kernel(const float* __restrict__ proto,
                  const float* __restrict__ W1,
                  const float* __restrict__ b1) {
    __shared__ __align__(16) float sW[3][PKC][132];
    __shared__ __align__(16) float sP[3][8][36];

    const int t = threadIdx.x;
    const int j = t & 127;
    const int pg = t >> 7;
    const int p0 = blockIdx.x * 8;

    const uint32_t wSm = smem_u32(sW);
    const uint32_t pSm = smem_u32(sP);

    auto load_stage = [&](int kc, int s) {
        const int k0 = kc * PKC;
#pragma unroll
        for (int r = 0; r < 4; r++) {
            int slot = t + r * 256;
            int row = slot >> 5, col = (slot & 31) * 4;
            cp_async16(wSm + (uint32_t)(s * (PKC * 132) + row * 132 + col) * 4,
                       W1 + (size_t)(EMBED + k0 + row) * HID + col);
        }
        if (t < 64) {
            int row = t >> 3, col = (t & 7) * 4;
            cp_async16(pSm + (uint32_t)(s * (8 * 36) + row * 36 + col) * 4,
                       proto + (size_t)(p0 + row) * EMBED + k0 + col);
        }
    };

    load_stage(0, 0); CP_COMMIT();
    load_stage(1, 1); CP_COMMIT();

    float acc0 = 0.f, acc1 = 0.f, acc2 = 0.f, acc3 = 0.f;
    for (int kc = 0; kc < PNI; kc++) {
        const int sc = kc % 3;
        CP_WAIT1();
        __syncthreads();
        if (kc + 2 < PNI) load_stage(kc + 2, (kc + 2) % 3);
        CP_COMMIT();
        const float (*W)[132] = sW[sc];
        const float (*P)[36]  = sP[sc];
#pragma unroll
        for (int k = 0; k < PKC; k++) {
            float w = W[k][j];
            acc0 += P[pg * 4 + 0][k] * w;
            acc1 += P[pg * 4 + 1][k] * w;
            acc2 += P[pg * 4 + 2][k] * w;
            acc3 += P[pg * 4 + 3][k] * w;
        }
        __syncthreads();
    }
    float bb = b1[j];
    g_Pb[(size_t)(p0 + pg * 4 + 0) * HID + j] = acc0 + bb;
    g_Pb[(size_t)(p0 + pg * 4 + 1) * HID + j] = acc1 + bb;
    g_Pb[(size_t)(p0 + pg * 4 + 2) * HID + j] = acc2 + bb;
    g_Pb[(size_t)(p0 + pg * 4 + 3) * HID + j] = acc3 + bb;
}

// ---------------------------------------------------------------------------
// Kernel 3: TMA-fed pipeline (unchanged skeleton from R16).
// Delta 1: B fragments hoisted per ks, reused across mi (halves B smem reads).
// Delta 2: TMA issue from warp 7 (argmin-free, compute-light warp).
// ---------------------------------------------------------------------------
__global__ __launch_bounds__(NTHR, 2)
void gemm_kernel(const __grid_constant__ CUtensorMap tmapA,
                 const float* __restrict__ dist,
                 const float* __restrict__ W2,
                 const float* __restrict__ b2,
                 float* __restrict__ out) {
    extern __shared__ __align__(16) char dyn_raw[];
    __shared__ __align__(8) uint64_t s_full[STAGES];
    __shared__ float s_w2[HID];
    __shared__ float s_rowsum[MT];
    __shared__ int   s_idx[MT];

    const int t = threadIdx.x, warp = t >> 5, lane = t & 31;
    const int m0 = blockIdx.x * MT;

    const uint32_t base_raw = smem_u32(dyn_raw);
    const uint32_t base = (base_raw + 1023u) & ~1023u;   // SW128 atom alignment
    char* dynA = dyn_raw + (base - base_raw);
    const uint32_t barBase = smem_u32(s_full);

    if (t == 0) {
#pragma unroll
        for (int s = 0; s < STAGES; s++) MBAR_INIT(barBase + s * 8, 1);
        FENCE_ASYNC();
    }
    if (t < HID) s_w2[t] = W2[t];
    if (t < MT)  s_rowsum[t] = 0.f;
    __syncthreads();

    const int issuer = (warp == 7) && elect_one();
    auto issue = [&](int c) {                      // single elected thread, warp 7
        const int s = c % STAGES;
        const uint32_t bar = barBase + s * 8;
        MBAR_EXPECT_TX(bar, STAGE_TX);
        tma_tile_2d(base + s * A_ST_BYTES, (const void*)&tmapA, c * KC, m0, bar);
        bulk_1d(base + A_TOT + s * B_ST_BYTES,
                g_W1t + (size_t)c * (HID * BPAD), B_ST_BYTES, bar);
        bulk_1d(base + A_TOT + B_TOT + s * D_ST_BYTES,
                dist + (size_t)(m0 + c * 4) * NP, D_ST_BYTES, bar);
    };

    if (issuer) { issue(0); issue(1); }

    // ---- accumulators + fragment mapping ----
    float acc[2][8][4];
#pragma unroll
    for (int mi = 0; mi < 2; mi++)
#pragma unroll
        for (int ni = 0; ni < 8; ni++)
#pragma unroll
            for (int r = 0; r < 4; r++) acc[mi][ni][r] = 0.f;

    const int warpM = warp >> 1;   // rows warpM*32
    const int warpN = warp & 1;    // cols warpN*64
    const int g  = lane >> 2;      // 0..7
    const int qd = lane & 3;       // 0..3
    const int gx = g * 4;          // SW128 xor term (fp32 units)

    for (int c = 0; c < NITER; c++) {
        const int sc = c % STAGES;
        if (issuer && c + 2 < NITER) issue(c + 2);
        MBAR_WAIT(barBase + sc * 8, (c / STAGES) & 1);

        const float*         A0 = (const float*)(dynA + sc * A_ST_BYTES);
        const __nv_bfloat16* B0 = (const __nv_bfloat16*)(dynA + A_TOT + sc * B_ST_BYTES);
        const float*         D0 = (const float*)(dynA + A_TOT + B_TOT + sc * D_ST_BYTES);

#pragma unroll
        for (int ks = 0; ks < 2; ks++) {
            const int ko = ks * 16;
            const int col0 = (ko + qd * 2) ^ gx;       // SW128 physical col
            const int col2 = (ko + qd * 2 + 8) ^ gx;

            // ---- B fragments: load ONCE per ks, reuse across both mi ----
            uint32_t b[8][2];
            const __nv_bfloat16* pb0 = B0 + (warpN * 64 + g) * BPAD + ko + qd * 2;
#pragma unroll
            for (int ni = 0; ni < 8; ni++) {
                b[ni][0] = *(const uint32_t*)(pb0 + ni * 8 * BPAD);
                b[ni][1] = *(const uint32_t*)(pb0 + ni * 8 * BPAD + 8);
            }
#pragma unroll
            for (int mi = 0; mi < 2; mi++) {
                const float* r1 = A0 + (warpM * 32 + mi * 16 + g) * 32;
                const float* r2 = r1 + 8 * 32;
                float2 v;
                uint32_t a0, a1, a2, a3;
                v = *(const float2*)(r1 + col0); a0 = cvt_bf2(v.y, v.x);
                v = *(const float2*)(r2 + col0); a1 = cvt_bf2(v.y, v.x);
                v = *(const float2*)(r1 + col2); a2 = cvt_bf2(v.y, v.x);
                v = *(const float2*)(r2 + col2); a3 = cvt_bf2(v.y, v.x);
#pragma unroll
                for (int ni = 0; ni < 8; ni++) {
                    asm volatile(
                        "mma.sync.aligned.m16n8k16.row.col.f32.bf16.bf16.f32 "
                        "{%0,%1,%2,%3}, {%4,%5,%6,%7}, {%8,%9}, {%0,%1,%2,%3};\n"
                        : "+f"(acc[mi][ni][0]), "+f"(acc[mi][ni][1]),
                          "+f"(acc[mi][ni][2]), "+f"(acc[mi][ni][3])
                        : "r"(a0), "r"(a1), "r"(a2), "r"(a3),
                          "r"(b[ni][0]), "r"(b[ni][1]));
                }
            }
        }

        // ---- argmin fold: warps 0-3 each fold one of this stage's 4 rows ----
        if (warp < 4) {
            const float* drow = D0 + warp * NP;
            float best = 3.4e38f; int bi = 0;
#pragma unroll
            for (int it = 0; it < 4; it++) {
                int jj = it * 128 + lane * 4;
                float4 v = *(const float4*)(drow + jj);
                if (v.x < best) { best = v.x; bi = jj; }
                if (v.y < best) { best = v.y; bi = jj + 1; }
                if (v.z < best) { best = v.z; bi = jj + 2; }
                if (v.w < best) { best = v.w; bi = jj + 3; }
            }
#pragma unroll
            for (int off = 16; off; off >>= 1) {
                float ov = __shfl_down_sync(0xffffffffu, best, off);
                int   oi = __shfl_down_sync(0xffffffffu, bi,   off);
                if (ov < best || (ov == best && oi < bi)) { best = ov; bi = oi; }
            }
            if (lane == 0) s_idx[c * 4 + warp] = bi;
        }
        __syncthreads();    // stage sc fully consumed before re-issue
    }

    // ---- epilogue: +Pb[idx], relu, * W2, quad-reduce, atomic, sigmoid ----
#pragma unroll
    for (int mi = 0; mi < 2; mi++) {
#pragma unroll
        for (int rr = 0; rr < 2; rr++) {
            int rloc = warpM * 32 + mi * 16 + rr * 8 + g;
            const float* Pr = g_Pb + (size_t)s_idx[rloc] * HID;
            float s = 0.f;
#pragma unroll
            for (int ni = 0; ni < 8; ni++) {
                int cc = warpN * 64 + ni * 8 + qd * 2;
                float v0 = acc[mi][ni][rr * 2 + 0] + Pr[cc];
                float v1 = acc[mi][ni][rr * 2 + 1] + Pr[cc + 1];
                s += fmaxf(v0, 0.f) * s_w2[cc] + fmaxf(v1, 0.f) * s_w2[cc + 1];
            }
            s += __shfl_xor_sync(0xffffffffu, s, 1);
            s += __shfl_xor_sync(0xffffffffu, s, 2);
            if (qd == 0) atomicAdd(&s_rowsum[rloc], s);
        }
    }
    __syncthreads();
    if (t < MT) {
        float z = s_rowsum[t] + b2[0];
        out[m0 + t] = 1.f / (1.f + __expf(-z));
    }
}

// ---------------------------------------------------------------------------
typedef CUresult (CUDAAPI *EncodeFn)(
    CUtensorMap*, CUtensorMapDataType, cuuint32_t, void*,
    const cuuint64_t*, const cuuint64_t*, const cuuint32_t*, const cuuint32_t*,
    CUtensorMapInterleave, CUtensorMapSwizzle, CUtensorMapL2promotion,
    CUtensorMapFloatOOBfill);

extern "C" void kernel_launch(void* const* d_in, const int* in_sizes, int n_in,
                              void* d_out, int out_size) {
    const float* Q     = (const float*)d_in[0];   // [65536,1024]
    const float* proto = (const float*)d_in[1];   // [512,1024]
    const float* dist  = (const float*)d_in[2];   // [65536,512]
    const float* W1    = (const float*)d_in[3];   // [2048,128]
    const float* b1    = (const float*)d_in[4];   // [128]
    const float* W2    = (const float*)d_in[5];   // [128,1]
    const float* b2    = (const float*)d_in[6];   // [1]
    float* out = (float*)d_out;                   // [65536]

    static EncodeFn enc = nullptr;
    static bool attr_set = false;
    if (!attr_set) {
        cudaFuncSetAttribute(gemm_kernel,
                             cudaFuncAttributeMaxDynamicSharedMemorySize, DYN_SMEM);
        attr_set = true;
    }
    if (!enc) {
        cudaDriverEntryPointQueryResult qr;
#if CUDART_VERSION >= 12050
        cudaGetDriverEntryPointByVersion("cuTensorMapEncodeTiled", (void**)&enc,
                                         12000, cudaEnableDefault, &qr);
#endif
        if (!enc)
            cudaGetDriverEntryPoint("cuTensorMapEncodeTiled", (void**)&enc,
                                    cudaEnableDefault, &qr);
    }

    CUtensorMap tmapA;
    {
        cuuint64_t dims[2]    = {EMBED, NQ};
        cuuint64_t strides[1] = {EMBED * sizeof(float)};
        cuuint32_t box[2]     = {KC, MT};            // 32 fp32 = 128B = SW128 limit
        cuuint32_t estr[2]    = {1, 1};
        enc(&tmapA, CU_TENSOR_MAP_DATA_TYPE_FLOAT32, 2, (void*)Q,
            dims, strides, box, estr,
            CU_TENSOR_MAP_INTERLEAVE_NONE, CU_TENSOR_MAP_SWIZZLE_128B,
            CU_TENSOR_MAP_L2_PROMOTION_L2_128B, CU_TENSOR_MAP_FLOAT_OOB_FILL_NONE);
    }

    w1t_kernel<<<dim3(EMBED / 32, HID / 32), dim3(32, 8)>>>(W1);
    proto_kernel<<<NP / 8, 256>>>(proto, W1, b1);
    gemm_kernel<<<NQ / MT, NTHR, DYN_SMEM>>>(tmapA, dist, W2, b2, out);
}